// round 6
// baseline (speedup 1.0000x reference)
#include <cuda_runtime.h>
#include <cuda_fp16.h>
#include <cstdint>

// ============================================================================
// ECGRGNN via warp-level mma.sync (base sm_100; tcgen05 unavailable here).
//
// GRU matvec per step: D[192 gates, 48 nodes] = W_hh[192,64] @ h[48,64]^T,
// m16n8k16 fp16 mma, 3-term precision split (fp32 accum):
//   D = Whi*hhi + Whi*hlo + Wlo*hhi
//
// R6: ILP restructure. Per warp per step: (1) load ALL h fragments for the
// group's 3 node tiles (24 independent ldmatrix), (2) 108 mma in 9
// independent accumulator chains interleaved, (3) all 12 gate elements in
// one batch (12 independent MUFU chains). wa_lo fragments are re-ldmatrix'd
// per k-chunk instead of register-resident to stay under the 255-reg cap.
// 8 warps/CTA (2/SMSP); groups sync on separate named barriers.
// ============================================================================

#define T_LEN 500
#define N_NODES 6144
#define NCTA 128
#define NODES_CTA 48
#define CTA_THREADS 256

typedef uint32_t u32;

__device__ float g_h[N_NODES * 64];

// ---------------- SMEM layout (byte offsets) ----------------
#define SM_W_HI 0                    // 192 rows x 128B (fp16, swz)   24576
#define SM_W_LO 24576                //                               24576
#define SM_H    49152                // 2 buf x 2 split x 48x128B     24576
#define SM_X    73728                // 500 x 48 f32                  96000
#define SMEM_TOTAL 169728

// ---------------- helpers ----------------

__device__ __forceinline__ u32 smem_u32(const void* p) {
    u32 a;
    asm("{ .reg .u64 t; cvta.to.shared.u64 t, %1; cvt.u32.u64 %0, t; }" : "=r"(a) : "l"(p));
    return a;
}
__device__ __forceinline__ u32 swz(u32 off) { return off ^ ((off >> 3) & 0x70); }

__device__ __forceinline__ void ldsm_x4(u32* r, u32 addr) {
    asm volatile("ldmatrix.sync.aligned.m8n8.x4.shared.b16 {%0,%1,%2,%3}, [%4];"
        : "=r"(r[0]), "=r"(r[1]), "=r"(r[2]), "=r"(r[3]) : "r"(addr));
}
__device__ __forceinline__ void ldsm_x2(u32* r, u32 addr) {
    asm volatile("ldmatrix.sync.aligned.m8n8.x2.shared.b16 {%0,%1}, [%2];"
        : "=r"(r[0]), "=r"(r[1]) : "r"(addr));
}
__device__ __forceinline__ void mma16816(float* d, const u32* a, const u32* b) {
    asm volatile("mma.sync.aligned.m16n8k16.row.col.f32.f16.f16.f32 "
        "{%0,%1,%2,%3}, {%4,%5,%6,%7}, {%8,%9}, {%0,%1,%2,%3};"
        : "+f"(d[0]), "+f"(d[1]), "+f"(d[2]), "+f"(d[3])
        : "r"(a[0]), "r"(a[1]), "r"(a[2]), "r"(a[3]), "r"(b[0]), "r"(b[1]));
}

__device__ __forceinline__ float ex2a(float x) { float r; asm("ex2.approx.f32 %0, %1;" : "=f"(r) : "f"(x)); return r; }
__device__ __forceinline__ float rcpa(float x) { float r; asm("rcp.approx.f32 %0, %1;" : "=f"(r) : "f"(x)); return r; }
__device__ __forceinline__ float sigm(float v) { return rcpa(1.0f + ex2a(v * -1.4426950408889634f)); }
__device__ __forceinline__ float tanh_fast(float v) { return fmaf(2.0f, rcpa(1.0f + ex2a(v * -2.8853900817779268f)), -1.0f); }

// ---------------- GRU kernel ----------------

__global__ void __launch_bounds__(CTA_THREADS, 1)
gru_mma_kernel(const float* __restrict__ x_raw,
               const float* __restrict__ w_ih,
               const float* __restrict__ w_hh,
               const float* __restrict__ b_ih,
               const float* __restrict__ b_hh)
{
    extern __shared__ char sm[];
    const u32 smb = smem_u32(sm);
    const int tid = threadIdx.x;
    const int lane = tid & 31;
    const int wid = tid >> 5;
    const int q = wid & 3;                  // m-tile selector (gate-row block)
    const int grp = wid >> 2;               // warp group: 0 -> nt 0-2, 1 -> nt 3-5
    const int nt0 = grp * 3;
    const int bar_id = 1 + grp;
    const int gn0 = blockIdx.x * NODES_CTA;

    // ---- stage W_hh fp16 splits (192 x 64, 128B rows, swizzled) ----
    for (int i = tid; i < 192 * 64; i += CTA_THREADS) {
        int r = i >> 6, k = i & 63;
        float w = w_hh[i];
        __half hi = __float2half_rn(w);
        __half lo = __float2half_rn(w - __half2float(hi));
        u32 off = swz((u32)(r * 128 + k * 2));
        *(__half*)(sm + SM_W_HI + off) = hi;
        *(__half*)(sm + SM_W_LO + off) = lo;
    }
    // ---- zero h tiles (both buffers, both splits) ----
    for (int i = tid; i < 24576 / 4; i += CTA_THREADS)
        ((u32*)(sm + SM_H))[i] = 0u;
    // ---- stage x transposed: xs[t*48 + n] ----
    {
        float* xs = (float*)(sm + SM_X);
        for (int i = tid; i < NODES_CTA * T_LEN; i += CTA_THREADS) {
            int n = i / T_LEN, tt = i - n * T_LEN;
            xs[tt * NODES_CTA + n] = x_raw[(size_t)(gn0 + n) * T_LEN + tt];
        }
    }
    __syncthreads();

    // ---- W fragment addresses + preload wa_hi (A operand, row-major) ----
    u32 wa_hi[3][4][4];
    u32 wlo_addr[3][4];
    {
        int g = lane >> 3;
        int sub_m = (g & 1) * 8;
        int sub_kb = (g >> 1) * 16;
#pragma unroll
        for (int mt = 0; mt < 3; mt++) {
#pragma unroll
            for (int kc = 0; kc < 4; kc++) {
                int row = 64 * mt + 16 * q + sub_m + (lane & 7);
                u32 off = (u32)row * 128 + (u32)((kc * 32 + sub_kb) ^ ((row & 7) << 4));
                ldsm_x4(wa_hi[mt][kc], smb + SM_W_HI + off);
                wlo_addr[mt][kc] = smb + SM_W_LO + off;
            }
        }
    }

    // ---- per-thread gate constants: units u_a = 16q + lane/4, u_b = u_a+8 ----
    const int u_a = 16 * q + (lane >> 2);
    const int u_b = u_a + 8;
    const float cwr_a = w_ih[u_a],        cwr_b = w_ih[u_b];
    const float cwz_a = w_ih[64 + u_a],   cwz_b = w_ih[64 + u_b];
    const float cwn_a = w_ih[128 + u_a],  cwn_b = w_ih[128 + u_b];
    const float cr_a  = b_ih[u_a] + b_hh[u_a];
    const float cr_b  = b_ih[u_b] + b_hh[u_b];
    const float cz_a  = b_ih[64 + u_a] + b_hh[64 + u_a];
    const float cz_b  = b_ih[64 + u_b] + b_hh[64 + u_b];
    const float cbin_a = b_ih[128 + u_a], cbin_b = b_ih[128 + u_b];
    const float cbhn_a = b_hh[128 + u_a], cbhn_b = b_hh[128 + u_b];

    // ---- h-fragment (B operand) lane addressing ----
    const int l15 = lane & 15;
    const int r7 = l15 & 7;
    const int xorv = r7 << 4;
    u32 ko[4];
#pragma unroll
    for (int kc = 0; kc < 4; kc++)
        ko[kc] = (u32)((kc * 32 + ((l15 >> 3) * 16)) ^ xorv);
    const u32 hrow_off = (u32)r7 * 128;

    const int nc = 2 * (lane & 3);
    const float* xs = (const float*)(sm + SM_X);

    float hprev[3][4];
#pragma unroll
    for (int j = 0; j < 3; j++)
#pragma unroll
        for (int i = 0; i < 4; i++) hprev[j][i] = 0.0f;

#pragma unroll 1
    for (int t = 0; t < T_LEN; t++) {
        const int buf = t & 1;
        const u32 rd_hi = smb + SM_H + (u32)buf * 12288;
        const u32 rd_lo = rd_hi + 6144;
        char* wr_hi = sm + SM_H + (buf ^ 1) * 12288;
        char* wr_lo = wr_hi + 6144;
        const float* xrow = xs + t * NODES_CTA;

        // ---- phase 1: load ALL h fragments for this group's 3 tiles ----
        u32 hh[3][4][2], hl[3][4][2];
#pragma unroll
        for (int j = 0; j < 3; j++) {
            u32 base = (u32)((nt0 + j) * 1024) + hrow_off;
#pragma unroll
            for (int kc = 0; kc < 4; kc++) {
                ldsm_x2(hh[j][kc], rd_hi + base + ko[kc]);
                ldsm_x2(hl[j][kc], rd_lo + base + ko[kc]);
            }
        }

        // ---- phase 2: 108 mma in 9 independent accumulator chains ----
        float acc[3][3][4];   // [tile][mt][frag]
#pragma unroll
        for (int j = 0; j < 3; j++)
#pragma unroll
            for (int mt = 0; mt < 3; mt++)
#pragma unroll
                for (int i = 0; i < 4; i++) acc[j][mt][i] = 0.0f;

#pragma unroll
        for (int kc = 0; kc < 4; kc++) {
            u32 wlo3[3][4];
#pragma unroll
            for (int mt = 0; mt < 3; mt++) ldsm_x4(wlo3[mt], wlo_addr[mt][kc]);
#pragma unroll
            for (int j = 0; j < 3; j++)
#pragma unroll
                for (int mt = 0; mt < 3; mt++)
                    mma16816(acc[j][mt], wa_hi[mt][kc], hh[j][kc]);
#pragma unroll
            for (int j = 0; j < 3; j++)
#pragma unroll
                for (int mt = 0; mt < 3; mt++)
                    mma16816(acc[j][mt], wa_hi[mt][kc], hl[j][kc]);
#pragma unroll
            for (int j = 0; j < 3; j++)
#pragma unroll
                for (int mt = 0; mt < 3; mt++)
                    mma16816(acc[j][mt], wlo3[mt], hh[j][kc]);
        }

        // ---- phase 3: all 12 gate elements batched (12 MUFU chains) ----
#pragma unroll
        for (int j = 0; j < 3; j++) {
            const int nt = nt0 + j;
            const int n_a = nt * 8 + nc;
            const float xva = xrow[n_a];
            const float xvb = xrow[n_a + 1];
#pragma unroll
            for (int i = 0; i < 4; i++) {
                const bool ub = (i >= 2);
                const float x = (i & 1) ? xvb : xva;
                const float cwr = ub ? cwr_b : cwr_a;
                const float cwz = ub ? cwz_b : cwz_a;
                const float cwn = ub ? cwn_b : cwn_a;
                const float cr  = ub ? cr_b  : cr_a;
                const float cz  = ub ? cz_b  : cz_a;
                const float cbin = ub ? cbin_b : cbin_a;
                const float cbhn = ub ? cbhn_b : cbhn_a;

                float rr = sigm(acc[j][0][i] + fmaf(x, cwr, cr));
                float zz = sigm(acc[j][1][i] + fmaf(x, cwz, cz));
                float nn = tanh_fast(fmaf(rr, acc[j][2][i] + cbhn, fmaf(x, cwn, cbin)));
                float hp = hprev[j][i];
                float hn = fmaf(zz, hp - nn, nn);
                hprev[j][i] = hn;

                __half hi = __float2half_rn(hn);
                __half lo = __float2half_rn(hn - __half2float(hi));
                int node = n_a + (i & 1);
                int u = ub ? u_b : u_a;
                u32 off = (u32)node * 128 + (u32)((u * 2) ^ ((node & 7) << 4));
                *(__half*)(wr_hi + off) = hi;
                *(__half*)(wr_lo + off) = lo;
            }
        }
        // per-group barrier (groups are independent: disjoint h tiles)
        asm volatile("bar.sync %0, %1;" :: "r"(bar_id), "r"(128) : "memory");
    }

    // ---- write final h ----
#pragma unroll
    for (int j = 0; j < 3; j++) {
#pragma unroll
        for (int i = 0; i < 4; i++) {
            int node = (nt0 + j) * 8 + nc + (i & 1);
            int u = (i >= 2) ? u_b : u_a;
            g_h[(size_t)(gn0 + node) * 64 + u] = hprev[j][i];
        }
    }
}

// ---------------- collapsed GCN head ----------------

__global__ void __launch_bounds__(128)
head_kernel(const float* __restrict__ W1, const float* __restrict__ b1,
            const float* __restrict__ W2, const float* __restrict__ b2,
            const float* __restrict__ Wfc, const float* __restrict__ bfc,
            float* __restrict__ out)
{
    __shared__ float hbar[64];
    __shared__ float x1s[128];
    __shared__ float x2s[128];
    int g = blockIdx.x, tid = threadIdx.x;

    if (tid < 64) {
        float s = 0.0f;
#pragma unroll
        for (int l = 0; l < 12; l++)
            s += g_h[(size_t)(g * 12 + l) * 64 + tid];
        hbar[tid] = s * (1.0f / 12.0f);
    }
    __syncthreads();

    float s = b1[tid];
#pragma unroll
    for (int k = 0; k < 64; k++)
        s = fmaf(hbar[k], W1[k * 128 + tid], s);
    x1s[tid] = fmaxf(s, 0.0f);
    __syncthreads();

    float s2 = b2[tid];
#pragma unroll
    for (int k = 0; k < 128; k++)
        s2 = fmaf(x1s[k], W2[k * 128 + tid], s2);
    x2s[tid] = fmaxf(s2, 0.0f);
    __syncthreads();

    if (tid < 5) {
        float o = bfc[tid];
#pragma unroll
        for (int k = 0; k < 128; k++)
            o = fmaf(x2s[k], Wfc[k * 5 + tid], o);
        out[g * 5 + tid] = o;
    }
}

// ---------------- launch ----------------
// metadata order: 0 x_raw, 1 edge_index, 2 batch, 3 w_ih, 4 w_hh, 5 b_ih,
//                 6 b_hh, 7 W1, 8 b1, 9 W2, 10 b2, 11 Wfc, 12 bfc

extern "C" void kernel_launch(void* const* d_in, const int* in_sizes, int n_in,
                              void* d_out, int out_size)
{
    const float* x_raw = (const float*)d_in[0];
    const float* w_ih  = (const float*)d_in[3];
    const float* w_hh  = (const float*)d_in[4];
    const float* b_ih  = (const float*)d_in[5];
    const float* b_hh  = (const float*)d_in[6];
    const float* W1    = (const float*)d_in[7];
    const float* b1    = (const float*)d_in[8];
    const float* W2    = (const float*)d_in[9];
    const float* b2    = (const float*)d_in[10];
    const float* Wfc   = (const float*)d_in[11];
    const float* bfc   = (const float*)d_in[12];
    float* out = (float*)d_out;

    cudaFuncSetAttribute(gru_mma_kernel, cudaFuncAttributeMaxDynamicSharedMemorySize, SMEM_TOTAL);

    gru_mma_kernel<<<NCTA, CTA_THREADS, SMEM_TOTAL>>>(x_raw, w_ih, w_hh, b_ih, b_hh);
    head_kernel<<<512, 128>>>(W1, b1, W2, b2, Wfc, bfc, out);
}

// round 7
// speedup vs baseline: 1.0530x; 1.0530x over previous
#include <cuda_runtime.h>
#include <cuda_fp16.h>
#include <cstdint>

// ============================================================================
// ECGRGNN via warp-level mma.sync (base sm_100; tcgen05 unavailable here).
//
// GRU matvec per step: D[192 gates, 48 nodes] = W_hh[192,64] @ h[48,64]^T,
// m16n8k16 fp16 mma, 3-term precision split (fp32 accum):
//   D = Whi*hhi + Whi*hlo + Wlo*hhi
//
// R7: occupancy push. 12 warps/CTA (3 per SMSP) for latency hiding, with the
// register budget engineered under the 170-reg cap at 384 threads:
//  - wa_hi fragments resident (48 regs); wa_lo reloaded per k-chunk via
//    ldsm.x4 from 3 base addrs + 4 shared swizzle offsets (row&7 == lane&7
//    is m-tile invariant, so the offset table is shared).
//  - 3 groups x 4 warps; each group owns 2 node tiles, processed
//    sequentially (R5 structure: small transient live set, no spills).
//  - per-group named barriers; groups fully independent.
// Gates computed entirely in registers; one pack+store per element.
// ============================================================================

#define T_LEN 500
#define N_NODES 6144
#define NCTA 128
#define NODES_CTA 48
#define CTA_THREADS 384

typedef uint32_t u32;

__device__ float g_h[N_NODES * 64];

// ---------------- SMEM layout (byte offsets) ----------------
#define SM_W_HI 0                    // 192 rows x 128B (fp16, swz)   24576
#define SM_W_LO 24576                //                               24576
#define SM_H    49152                // 2 buf x 2 split x 48x128B     24576
#define SM_X    73728                // 500 x 48 f32                  96000
#define SMEM_TOTAL 169728

// ---------------- helpers ----------------

__device__ __forceinline__ u32 smem_u32(const void* p) {
    u32 a;
    asm("{ .reg .u64 t; cvta.to.shared.u64 t, %1; cvt.u32.u64 %0, t; }" : "=r"(a) : "l"(p));
    return a;
}
__device__ __forceinline__ u32 swz(u32 off) { return off ^ ((off >> 3) & 0x70); }

__device__ __forceinline__ void ldsm_x4(u32* r, u32 addr) {
    asm volatile("ldmatrix.sync.aligned.m8n8.x4.shared.b16 {%0,%1,%2,%3}, [%4];"
        : "=r"(r[0]), "=r"(r[1]), "=r"(r[2]), "=r"(r[3]) : "r"(addr));
}
__device__ __forceinline__ void ldsm_x2(u32* r, u32 addr) {
    asm volatile("ldmatrix.sync.aligned.m8n8.x2.shared.b16 {%0,%1}, [%2];"
        : "=r"(r[0]), "=r"(r[1]) : "r"(addr));
}
__device__ __forceinline__ void mma16816(float* d, const u32* a, const u32* b) {
    asm volatile("mma.sync.aligned.m16n8k16.row.col.f32.f16.f16.f32 "
        "{%0,%1,%2,%3}, {%4,%5,%6,%7}, {%8,%9}, {%0,%1,%2,%3};"
        : "+f"(d[0]), "+f"(d[1]), "+f"(d[2]), "+f"(d[3])
        : "r"(a[0]), "r"(a[1]), "r"(a[2]), "r"(a[3]), "r"(b[0]), "r"(b[1]));
}

__device__ __forceinline__ float ex2a(float x) { float r; asm("ex2.approx.f32 %0, %1;" : "=f"(r) : "f"(x)); return r; }
__device__ __forceinline__ float rcpa(float x) { float r; asm("rcp.approx.f32 %0, %1;" : "=f"(r) : "f"(x)); return r; }
__device__ __forceinline__ float sigm(float v) { return rcpa(1.0f + ex2a(v * -1.4426950408889634f)); }
__device__ __forceinline__ float tanh_fast(float v) { return fmaf(2.0f, rcpa(1.0f + ex2a(v * -2.8853900817779268f)), -1.0f); }

// ---------------- GRU kernel ----------------

__global__ void __launch_bounds__(CTA_THREADS, 1)
gru_mma_kernel(const float* __restrict__ x_raw,
               const float* __restrict__ w_ih,
               const float* __restrict__ w_hh,
               const float* __restrict__ b_ih,
               const float* __restrict__ b_hh)
{
    extern __shared__ char sm[];
    const u32 smb = smem_u32(sm);
    const int tid = threadIdx.x;
    const int lane = tid & 31;
    const int wid = tid >> 5;
    const int q = wid & 3;                  // m-tile selector (gate-row block)
    const int grp = wid >> 2;               // group 0..2 -> node tiles {2g, 2g+1}
    const int nt0 = grp * 2;
    const int bar_id = 1 + grp;
    const int gn0 = blockIdx.x * NODES_CTA;

    // ---- stage W_hh fp16 splits (192 x 64, 128B rows, swizzled) ----
    for (int i = tid; i < 192 * 64; i += CTA_THREADS) {
        int r = i >> 6, k = i & 63;
        float w = w_hh[i];
        __half hi = __float2half_rn(w);
        __half lo = __float2half_rn(w - __half2float(hi));
        u32 off = swz((u32)(r * 128 + k * 2));
        *(__half*)(sm + SM_W_HI + off) = hi;
        *(__half*)(sm + SM_W_LO + off) = lo;
    }
    // ---- zero h tiles (both buffers, both splits) ----
    for (int i = tid; i < 24576 / 4; i += CTA_THREADS)
        ((u32*)(sm + SM_H))[i] = 0u;
    // ---- stage x transposed: xs[t*48 + n] ----
    {
        float* xs = (float*)(sm + SM_X);
        for (int i = tid; i < NODES_CTA * T_LEN; i += CTA_THREADS) {
            int n = i / T_LEN, tt = i - n * T_LEN;
            xs[tt * NODES_CTA + n] = x_raw[(size_t)(gn0 + n) * T_LEN + tt];
        }
    }
    __syncthreads();

    // ---- W fragments: wa_hi resident; wa_lo via 3 bases + 4 shared offsets ----
    // row&7 == lane&7 for every m-tile, so the swizzled kc-offset table is
    // shared across m-tiles.
    u32 wa_hi[3][4][4];
    u32 wlobase[3];
    u32 wko[4];
    {
        int g = lane >> 3;
        int sub_m = (g & 1) * 8;
        int sub_kb = (g >> 1) * 16;
        int xorr = (lane & 7) << 4;
#pragma unroll
        for (int kc = 0; kc < 4; kc++)
            wko[kc] = (u32)((kc * 32 + sub_kb) ^ xorr);
#pragma unroll
        for (int mt = 0; mt < 3; mt++) {
            int row = 64 * mt + 16 * q + sub_m + (lane & 7);
            wlobase[mt] = smb + SM_W_LO + (u32)row * 128;
            u32 hibase = smb + SM_W_HI + (u32)row * 128;
#pragma unroll
            for (int kc = 0; kc < 4; kc++)
                ldsm_x4(wa_hi[mt][kc], hibase + wko[kc]);
        }
    }

    // ---- per-thread gate constants: units u_a = 16q + lane/4, u_b = u_a+8 ----
    const int u_a = 16 * q + (lane >> 2);
    const int u_b = u_a + 8;
    const float cwr_a = w_ih[u_a],        cwr_b = w_ih[u_b];
    const float cwz_a = w_ih[64 + u_a],   cwz_b = w_ih[64 + u_b];
    const float cwn_a = w_ih[128 + u_a],  cwn_b = w_ih[128 + u_b];
    const float cr_a  = b_ih[u_a] + b_hh[u_a];
    const float cr_b  = b_ih[u_b] + b_hh[u_b];
    const float cz_a  = b_ih[64 + u_a] + b_hh[64 + u_a];
    const float cz_b  = b_ih[64 + u_b] + b_hh[64 + u_b];
    const float cbin_a = b_ih[128 + u_a], cbin_b = b_ih[128 + u_b];
    const float cbhn_a = b_hh[128 + u_a], cbhn_b = b_hh[128 + u_b];

    // ---- h-fragment (B operand) lane addressing ----
    const int l15 = lane & 15;
    const int r7 = l15 & 7;
    const int xorv = r7 << 4;
    u32 ko[4];
#pragma unroll
    for (int kc = 0; kc < 4; kc++)
        ko[kc] = (u32)((kc * 32 + ((l15 >> 3) * 16)) ^ xorv);
    const u32 hrow_off = (u32)r7 * 128;

    const int nc = 2 * (lane & 3);
    const float* xs = (const float*)(sm + SM_X);

    float hprev[2][4];
#pragma unroll
    for (int j = 0; j < 2; j++)
#pragma unroll
        for (int i = 0; i < 4; i++) hprev[j][i] = 0.0f;

#pragma unroll 1
    for (int t = 0; t < T_LEN; t++) {
        const int buf = t & 1;
        const u32 rd_hi = smb + SM_H + (u32)buf * 12288;
        const u32 rd_lo = rd_hi + 6144;
        char* wr_hi = sm + SM_H + (buf ^ 1) * 12288;
        char* wr_lo = wr_hi + 6144;
        const float* xrow = xs + t * NODES_CTA;

#pragma unroll
        for (int j = 0; j < 2; j++) {
            const int nt = nt0 + j;
            // ---- load h fragments for this tile ----
            u32 hh[4][2], hl[4][2];
            u32 base = (u32)(nt * 1024) + hrow_off;
#pragma unroll
            for (int kc = 0; kc < 4; kc++) {
                ldsm_x2(hh[kc], rd_hi + base + ko[kc]);
                ldsm_x2(hl[kc], rd_lo + base + ko[kc]);
            }
            // ---- 3-term mma: 3 accumulator chains interleaved ----
            float acc[3][4];
#pragma unroll
            for (int mt = 0; mt < 3; mt++)
#pragma unroll
                for (int i = 0; i < 4; i++) acc[mt][i] = 0.0f;
#pragma unroll
            for (int kc = 0; kc < 4; kc++) {
                u32 wlo3[3][4];
#pragma unroll
                for (int mt = 0; mt < 3; mt++) ldsm_x4(wlo3[mt], wlobase[mt] + wko[kc]);
#pragma unroll
                for (int mt = 0; mt < 3; mt++) mma16816(acc[mt], wa_hi[mt][kc], hh[kc]);
#pragma unroll
                for (int mt = 0; mt < 3; mt++) mma16816(acc[mt], wa_hi[mt][kc], hl[kc]);
#pragma unroll
                for (int mt = 0; mt < 3; mt++) mma16816(acc[mt], wlo3[mt], hh[kc]);
            }
            // ---- gates (registers only) ----
            const int n_a = nt * 8 + nc;
            const float xva = xrow[n_a];
            const float xvb = xrow[n_a + 1];
#pragma unroll
            for (int i = 0; i < 4; i++) {
                const bool ub = (i >= 2);
                const float x = (i & 1) ? xvb : xva;
                const float cwr = ub ? cwr_b : cwr_a;
                const float cwz = ub ? cwz_b : cwz_a;
                const float cwn = ub ? cwn_b : cwn_a;
                const float cr  = ub ? cr_b  : cr_a;
                const float cz  = ub ? cz_b  : cz_a;
                const float cbin = ub ? cbin_b : cbin_a;
                const float cbhn = ub ? cbhn_b : cbhn_a;

                float rr = sigm(acc[0][i] + fmaf(x, cwr, cr));
                float zz = sigm(acc[1][i] + fmaf(x, cwz, cz));
                float nn = tanh_fast(fmaf(rr, acc[2][i] + cbhn, fmaf(x, cwn, cbin)));
                float hp = hprev[j][i];
                float hn = fmaf(zz, hp - nn, nn);
                hprev[j][i] = hn;

                __half hi = __float2half_rn(hn);
                __half lo = __float2half_rn(hn - __half2float(hi));
                int node = n_a + (i & 1);
                int u = ub ? u_b : u_a;
                u32 off = (u32)node * 128 + (u32)((u * 2) ^ ((node & 7) << 4));
                *(__half*)(wr_hi + off) = hi;
                *(__half*)(wr_lo + off) = lo;
            }
        }
        // per-group barrier (groups are independent: disjoint h tiles)
        asm volatile("bar.sync %0, %1;" :: "r"(bar_id), "r"(128) : "memory");
    }

    // ---- write final h ----
#pragma unroll
    for (int j = 0; j < 2; j++) {
#pragma unroll
        for (int i = 0; i < 4; i++) {
            int node = (nt0 + j) * 8 + nc + (i & 1);
            int u = (i >= 2) ? u_b : u_a;
            g_h[(size_t)(gn0 + node) * 64 + u] = hprev[j][i];
        }
    }
}

// ---------------- collapsed GCN head ----------------

__global__ void __launch_bounds__(128)
head_kernel(const float* __restrict__ W1, const float* __restrict__ b1,
            const float* __restrict__ W2, const float* __restrict__ b2,
            const float* __restrict__ Wfc, const float* __restrict__ bfc,
            float* __restrict__ out)
{
    __shared__ float hbar[64];
    __shared__ float x1s[128];
    __shared__ float x2s[128];
    int g = blockIdx.x, tid = threadIdx.x;

    if (tid < 64) {
        float s = 0.0f;
#pragma unroll
        for (int l = 0; l < 12; l++)
            s += g_h[(size_t)(g * 12 + l) * 64 + tid];
        hbar[tid] = s * (1.0f / 12.0f);
    }
    __syncthreads();

    float s = b1[tid];
#pragma unroll
    for (int k = 0; k < 64; k++)
        s = fmaf(hbar[k], W1[k * 128 + tid], s);
    x1s[tid] = fmaxf(s, 0.0f);
    __syncthreads();

    float s2 = b2[tid];
#pragma unroll
    for (int k = 0; k < 128; k++)
        s2 = fmaf(x1s[k], W2[k * 128 + tid], s2);
    x2s[tid] = fmaxf(s2, 0.0f);
    __syncthreads();

    if (tid < 5) {
        float o = bfc[tid];
#pragma unroll
        for (int k = 0; k < 128; k++)
            o = fmaf(x2s[k], Wfc[k * 5 + tid], o);
        out[g * 5 + tid] = o;
    }
}

// ---------------- launch ----------------
// metadata order: 0 x_raw, 1 edge_index, 2 batch, 3 w_ih, 4 w_hh, 5 b_ih,
//                 6 b_hh, 7 W1, 8 b1, 9 W2, 10 b2, 11 Wfc, 12 bfc

extern "C" void kernel_launch(void* const* d_in, const int* in_sizes, int n_in,
                              void* d_out, int out_size)
{
    const float* x_raw = (const float*)d_in[0];
    const float* w_ih  = (const float*)d_in[3];
    const float* w_hh  = (const float*)d_in[4];
    const float* b_ih  = (const float*)d_in[5];
    const float* b_hh  = (const float*)d_in[6];
    const float* W1    = (const float*)d_in[7];
    const float* b1    = (const float*)d_in[8];
    const float* W2    = (const float*)d_in[9];
    const float* b2    = (const float*)d_in[10];
    const float* Wfc   = (const float*)d_in[11];
    const float* bfc   = (const float*)d_in[12];
    float* out = (float*)d_out;

    cudaFuncSetAttribute(gru_mma_kernel, cudaFuncAttributeMaxDynamicSharedMemorySize, SMEM_TOTAL);

    gru_mma_kernel<<<NCTA, CTA_THREADS, SMEM_TOTAL>>>(x_raw, w_ih, w_hh, b_ih, b_hh);
    head_kernel<<<512, 128>>>(W1, b1, W2, b2, Wfc, bfc, out);
}

// round 8
// speedup vs baseline: 1.0575x; 1.0043x over previous
#include <cuda_runtime.h>
#include <cuda_fp16.h>
#include <cstdint>

// ============================================================================
// ECGRGNN via warp-level mma.sync (base sm_100; tcgen05 unavailable here).
//
// GRU matvec per step: D[192 gates, 48 nodes] = W_hh[192,64] @ h[48,64]^T,
// m16n8k16 fp16 mma, 3-term precision split (fp32 accum):
//   D = Whi*hhi + Whi*hlo + Wlo*hhi
//
// R8: bank-conflict elimination via padded-stride tiles. All SMEM matrix
// tiles use a 144-byte row stride (36 words = 4-bank rotation per row) and
// NO xor swizzle:
//  - every ldmatrix phase reads 8 rows covering all 32 banks exactly once;
//  - the per-element h stores (4 distinct nodes per warp-op) land in
//    distinct banks; half-word pairs that share a bank share the same
//    32-bit word (write-merged). Previously every store was 4-way
//    conflicted (node*128 stride aliased all nodes to one bank).
// Structure otherwise = R7: 12 warps (3/SMSP), 3 groups x 4 warps, 2 node
// tiles per group, per-group named barriers, gates entirely in registers.
// ============================================================================

#define T_LEN 500
#define N_NODES 6144
#define NCTA 128
#define NODES_CTA 48
#define CTA_THREADS 384

#define ROW_STRIDE 144               // 128B data + 16B pad: 4-bank rotation/row

typedef uint32_t u32;

__device__ float g_h[N_NODES * 64];

// ---------------- SMEM layout (byte offsets) ----------------
#define SM_W_HI 0                    // 192 rows x 144B               27648
#define SM_W_LO 27648                //                               27648
#define SM_H    55296                // 2 buf x 2 split x 48x144B     27648
#define H_BUF_BYTES 13824            // one buffer (hi+lo)
#define H_SPLIT_BYTES 6912           // one split (48 x 144)
#define SM_X    82944                // 500 x 48 f32                  96000
#define SMEM_TOTAL 178944

// ---------------- helpers ----------------

__device__ __forceinline__ u32 smem_u32(const void* p) {
    u32 a;
    asm("{ .reg .u64 t; cvta.to.shared.u64 t, %1; cvt.u32.u64 %0, t; }" : "=r"(a) : "l"(p));
    return a;
}

__device__ __forceinline__ void ldsm_x4(u32* r, u32 addr) {
    asm volatile("ldmatrix.sync.aligned.m8n8.x4.shared.b16 {%0,%1,%2,%3}, [%4];"
        : "=r"(r[0]), "=r"(r[1]), "=r"(r[2]), "=r"(r[3]) : "r"(addr));
}
__device__ __forceinline__ void ldsm_x2(u32* r, u32 addr) {
    asm volatile("ldmatrix.sync.aligned.m8n8.x2.shared.b16 {%0,%1}, [%2];"
        : "=r"(r[0]), "=r"(r[1]) : "r"(addr));
}
__device__ __forceinline__ void mma16816(float* d, const u32* a, const u32* b) {
    asm volatile("mma.sync.aligned.m16n8k16.row.col.f32.f16.f16.f32 "
        "{%0,%1,%2,%3}, {%4,%5,%6,%7}, {%8,%9}, {%0,%1,%2,%3};"
        : "+f"(d[0]), "+f"(d[1]), "+f"(d[2]), "+f"(d[3])
        : "r"(a[0]), "r"(a[1]), "r"(a[2]), "r"(a[3]), "r"(b[0]), "r"(b[1]));
}

__device__ __forceinline__ float ex2a(float x) { float r; asm("ex2.approx.f32 %0, %1;" : "=f"(r) : "f"(x)); return r; }
__device__ __forceinline__ float rcpa(float x) { float r; asm("rcp.approx.f32 %0, %1;" : "=f"(r) : "f"(x)); return r; }
__device__ __forceinline__ float sigm(float v) { return rcpa(1.0f + ex2a(v * -1.4426950408889634f)); }
__device__ __forceinline__ float tanh_fast(float v) { return fmaf(2.0f, rcpa(1.0f + ex2a(v * -2.8853900817779268f)), -1.0f); }

// ---------------- GRU kernel ----------------

__global__ void __launch_bounds__(CTA_THREADS, 1)
gru_mma_kernel(const float* __restrict__ x_raw,
               const float* __restrict__ w_ih,
               const float* __restrict__ w_hh,
               const float* __restrict__ b_ih,
               const float* __restrict__ b_hh)
{
    extern __shared__ char sm[];
    const u32 smb = smem_u32(sm);
    const int tid = threadIdx.x;
    const int lane = tid & 31;
    const int wid = tid >> 5;
    const int q = wid & 3;                  // m-tile selector (gate-row block)
    const int grp = wid >> 2;               // group 0..2 -> node tiles {2g, 2g+1}
    const int nt0 = grp * 2;
    const int bar_id = 1 + grp;
    const int gn0 = blockIdx.x * NODES_CTA;

    // ---- stage W_hh fp16 splits (192 x 64, 144B row stride, NO swizzle) ----
    for (int i = tid; i < 192 * 64; i += CTA_THREADS) {
        int r = i >> 6, k = i & 63;
        float w = w_hh[i];
        __half hi = __float2half_rn(w);
        __half lo = __float2half_rn(w - __half2float(hi));
        u32 off = (u32)(r * ROW_STRIDE + k * 2);
        *(__half*)(sm + SM_W_HI + off) = hi;
        *(__half*)(sm + SM_W_LO + off) = lo;
    }
    // ---- zero h tiles (both buffers, both splits) ----
    for (int i = tid; i < 27648 / 4; i += CTA_THREADS)
        ((u32*)(sm + SM_H))[i] = 0u;
    // ---- stage x transposed: xs[t*48 + n] ----
    {
        float* xs = (float*)(sm + SM_X);
        for (int i = tid; i < NODES_CTA * T_LEN; i += CTA_THREADS) {
            int n = i / T_LEN, tt = i - n * T_LEN;
            xs[tt * NODES_CTA + n] = x_raw[(size_t)(gn0 + n) * T_LEN + tt];
        }
    }
    __syncthreads();

    // ---- W fragments: wa_hi resident; wa_lo via 3 bases + 4 shared offsets ----
    u32 wa_hi[3][4][4];
    u32 wlobase[3];
    u32 wko[4];
    {
        int g = lane >> 3;
        int sub_m = (g & 1) * 8;
        int sub_kb = (g >> 1) * 16;
#pragma unroll
        for (int kc = 0; kc < 4; kc++)
            wko[kc] = (u32)(kc * 32 + sub_kb);
#pragma unroll
        for (int mt = 0; mt < 3; mt++) {
            int row = 64 * mt + 16 * q + sub_m + (lane & 7);
            wlobase[mt] = smb + SM_W_LO + (u32)row * ROW_STRIDE;
            u32 hibase = smb + SM_W_HI + (u32)row * ROW_STRIDE;
#pragma unroll
            for (int kc = 0; kc < 4; kc++)
                ldsm_x4(wa_hi[mt][kc], hibase + wko[kc]);
        }
    }

    // ---- per-thread gate constants: units u_a = 16q + lane/4, u_b = u_a+8 ----
    const int u_a = 16 * q + (lane >> 2);
    const int u_b = u_a + 8;
    const float cwr_a = w_ih[u_a],        cwr_b = w_ih[u_b];
    const float cwz_a = w_ih[64 + u_a],   cwz_b = w_ih[64 + u_b];
    const float cwn_a = w_ih[128 + u_a],  cwn_b = w_ih[128 + u_b];
    const float cr_a  = b_ih[u_a] + b_hh[u_a];
    const float cr_b  = b_ih[u_b] + b_hh[u_b];
    const float cz_a  = b_ih[64 + u_a] + b_hh[64 + u_a];
    const float cz_b  = b_ih[64 + u_b] + b_hh[64 + u_b];
    const float cbin_a = b_ih[128 + u_a], cbin_b = b_ih[128 + u_b];
    const float cbhn_a = b_hh[128 + u_a], cbhn_b = b_hh[128 + u_b];

    // ---- h-fragment (B operand) lane addressing (no swizzle) ----
    const int l15 = lane & 15;
    const int r7 = l15 & 7;
    u32 ko[4];
#pragma unroll
    for (int kc = 0; kc < 4; kc++)
        ko[kc] = (u32)(kc * 32 + ((l15 >> 3) * 16));
    const u32 hrow_off = (u32)r7 * ROW_STRIDE;

    const int nc = 2 * (lane & 3);
    const float* xs = (const float*)(sm + SM_X);

    float hprev[2][4];
#pragma unroll
    for (int j = 0; j < 2; j++)
#pragma unroll
        for (int i = 0; i < 4; i++) hprev[j][i] = 0.0f;

#pragma unroll 1
    for (int t = 0; t < T_LEN; t++) {
        const int buf = t & 1;
        const u32 rd_hi = smb + SM_H + (u32)buf * H_BUF_BYTES;
        const u32 rd_lo = rd_hi + H_SPLIT_BYTES;
        char* wr_hi = sm + SM_H + (buf ^ 1) * H_BUF_BYTES;
        char* wr_lo = wr_hi + H_SPLIT_BYTES;
        const float* xrow = xs + t * NODES_CTA;

#pragma unroll
        for (int j = 0; j < 2; j++) {
            const int nt = nt0 + j;
            // ---- load h fragments for this tile ----
            u32 hh[4][2], hl[4][2];
            u32 base = (u32)(nt * 8) * ROW_STRIDE + hrow_off;
#pragma unroll
            for (int kc = 0; kc < 4; kc++) {
                ldsm_x2(hh[kc], rd_hi + base + ko[kc]);
                ldsm_x2(hl[kc], rd_lo + base + ko[kc]);
            }
            // ---- 3-term mma: 3 accumulator chains interleaved ----
            float acc[3][4];
#pragma unroll
            for (int mt = 0; mt < 3; mt++)
#pragma unroll
                for (int i = 0; i < 4; i++) acc[mt][i] = 0.0f;
#pragma unroll
            for (int kc = 0; kc < 4; kc++) {
                u32 wlo3[3][4];
#pragma unroll
                for (int mt = 0; mt < 3; mt++) ldsm_x4(wlo3[mt], wlobase[mt] + wko[kc]);
#pragma unroll
                for (int mt = 0; mt < 3; mt++) mma16816(acc[mt], wa_hi[mt][kc], hh[kc]);
#pragma unroll
                for (int mt = 0; mt < 3; mt++) mma16816(acc[mt], wa_hi[mt][kc], hl[kc]);
#pragma unroll
                for (int mt = 0; mt < 3; mt++) mma16816(acc[mt], wlo3[mt], hh[kc]);
            }
            // ---- gates (registers only) ----
            const int n_a = nt * 8 + nc;
            const float xva = xrow[n_a];
            const float xvb = xrow[n_a + 1];
#pragma unroll
            for (int i = 0; i < 4; i++) {
                const bool ub = (i >= 2);
                const float x = (i & 1) ? xvb : xva;
                const float cwr = ub ? cwr_b : cwr_a;
                const float cwz = ub ? cwz_b : cwz_a;
                const float cwn = ub ? cwn_b : cwn_a;
                const float cr  = ub ? cr_b  : cr_a;
                const float cz  = ub ? cz_b  : cz_a;
                const float cbin = ub ? cbin_b : cbin_a;
                const float cbhn = ub ? cbhn_b : cbhn_a;

                float rr = sigm(acc[0][i] + fmaf(x, cwr, cr));
                float zz = sigm(acc[1][i] + fmaf(x, cwz, cz));
                float nn = tanh_fast(fmaf(rr, acc[2][i] + cbhn, fmaf(x, cwn, cbin)));
                float hp = hprev[j][i];
                float hn = fmaf(zz, hp - nn, nn);
                hprev[j][i] = hn;

                __half hi = __float2half_rn(hn);
                __half lo = __float2half_rn(hn - __half2float(hi));
                int node = n_a + (i & 1);
                int u = ub ? u_b : u_a;
                u32 off = (u32)(node * ROW_STRIDE + u * 2);
                *(__half*)(wr_hi + off) = hi;
                *(__half*)(wr_lo + off) = lo;
            }
        }
        // per-group barrier (groups are independent: disjoint h tiles)
        asm volatile("bar.sync %0, %1;" :: "r"(bar_id), "r"(128) : "memory");
    }

    // ---- write final h ----
#pragma unroll
    for (int j = 0; j < 2; j++) {
#pragma unroll
        for (int i = 0; i < 4; i++) {
            int node = (nt0 + j) * 8 + nc + (i & 1);
            int u = (i >= 2) ? u_b : u_a;
            g_h[(size_t)(gn0 + node) * 64 + u] = hprev[j][i];
        }
    }
}

// ---------------- collapsed GCN head ----------------

__global__ void __launch_bounds__(128)
head_kernel(const float* __restrict__ W1, const float* __restrict__ b1,
            const float* __restrict__ W2, const float* __restrict__ b2,
            const float* __restrict__ Wfc, const float* __restrict__ bfc,
            float* __restrict__ out)
{
    __shared__ float hbar[64];
    __shared__ float x1s[128];
    __shared__ float x2s[128];
    int g = blockIdx.x, tid = threadIdx.x;

    if (tid < 64) {
        float s = 0.0f;
#pragma unroll
        for (int l = 0; l < 12; l++)
            s += g_h[(size_t)(g * 12 + l) * 64 + tid];
        hbar[tid] = s * (1.0f / 12.0f);
    }
    __syncthreads();

    float s = b1[tid];
#pragma unroll
    for (int k = 0; k < 64; k++)
        s = fmaf(hbar[k], W1[k * 128 + tid], s);
    x1s[tid] = fmaxf(s, 0.0f);
    __syncthreads();

    float s2 = b2[tid];
#pragma unroll
    for (int k = 0; k < 128; k++)
        s2 = fmaf(x1s[k], W2[k * 128 + tid], s2);
    x2s[tid] = fmaxf(s2, 0.0f);
    __syncthreads();

    if (tid < 5) {
        float o = bfc[tid];
#pragma unroll
        for (int k = 0; k < 128; k++)
            o = fmaf(x2s[k], Wfc[k * 5 + tid], o);
        out[g * 5 + tid] = o;
    }
}

// ---------------- launch ----------------
// metadata order: 0 x_raw, 1 edge_index, 2 batch, 3 w_ih, 4 w_hh, 5 b_ih,
//                 6 b_hh, 7 W1, 8 b1, 9 W2, 10 b2, 11 Wfc, 12 bfc

extern "C" void kernel_launch(void* const* d_in, const int* in_sizes, int n_in,
                              void* d_out, int out_size)
{
    const float* x_raw = (const float*)d_in[0];
    const float* w_ih  = (const float*)d_in[3];
    const float* w_hh  = (const float*)d_in[4];
    const float* b_ih  = (const float*)d_in[5];
    const float* b_hh  = (const float*)d_in[6];
    const float* W1    = (const float*)d_in[7];
    const float* b1    = (const float*)d_in[8];
    const float* W2    = (const float*)d_in[9];
    const float* b2    = (const float*)d_in[10];
    const float* Wfc   = (const float*)d_in[11];
    const float* bfc   = (const float*)d_in[12];
    float* out = (float*)d_out;

    cudaFuncSetAttribute(gru_mma_kernel, cudaFuncAttributeMaxDynamicSharedMemorySize, SMEM_TOTAL);

    gru_mma_kernel<<<NCTA, CTA_THREADS, SMEM_TOTAL>>>(x_raw, w_ih, w_hh, b_ih, b_hh);
    head_kernel<<<512, 128>>>(W1, b1, W2, b2, Wfc, bfc, out);
}

// round 10
// speedup vs baseline: 1.2170x; 1.1508x over previous
#include <cuda_runtime.h>
#include <cuda_fp16.h>
#include <cstdint>

// ============================================================================
// ECGRGNN via warp-level mma.sync (base sm_100; tcgen05 unavailable here).
//
// R9 (resubmitted after infra failure): the kernel is pinned at the
// legacy-HMMA tensor roofline (~512 MAC/cyc/SM: R5/R7/R8 all ~895us
// regardless of occupancy/conflicts). So: reduce tensor work.
// 3-term split -> 2-term split:
//   D = Whi*h16 + Wlo*h16        (h stored as single fp16; W split hi+lo)
// Only error source vs 3-term is h-input quantization (2^-12 rel, fresh each
// step, damped by the contractive update; hprev itself stays fp32 in regs).
// Tensor work drops 33%; hlo ldsm/pack/store disappear.
// Structure = R8: 12 warps (3/SMSP), 3 groups x 4 warps x 2 node tiles,
// 144B padded-stride tiles (conflict-free, no swizzle), per-group barriers,
// gates entirely in registers.
// ============================================================================

#define T_LEN 500
#define N_NODES 6144
#define NCTA 128
#define NODES_CTA 48
#define CTA_THREADS 384

#define ROW_STRIDE 144               // 128B data + 16B pad: 4-bank rotation/row

typedef uint32_t u32;

__device__ float g_h[N_NODES * 64];

// ---------------- SMEM layout (byte offsets) ----------------
#define SM_W_HI 0                    // 192 rows x 144B               27648
#define SM_W_LO 27648                //                               27648
#define SM_H    55296                // 2 buf x 48x144B               13824
#define H_BUF_BYTES 6912             // one buffer (fp16 h)
#define SM_X    69120                // 500 x 48 f32                  96000
#define SMEM_TOTAL 165120

// ---------------- helpers ----------------

__device__ __forceinline__ u32 smem_u32(const void* p) {
    u32 a;
    asm("{ .reg .u64 t; cvta.to.shared.u64 t, %1; cvt.u32.u64 %0, t; }" : "=r"(a) : "l"(p));
    return a;
}

__device__ __forceinline__ void ldsm_x4(u32* r, u32 addr) {
    asm volatile("ldmatrix.sync.aligned.m8n8.x4.shared.b16 {%0,%1,%2,%3}, [%4];"
        : "=r"(r[0]), "=r"(r[1]), "=r"(r[2]), "=r"(r[3]) : "r"(addr));
}
__device__ __forceinline__ void ldsm_x2(u32* r, u32 addr) {
    asm volatile("ldmatrix.sync.aligned.m8n8.x2.shared.b16 {%0,%1}, [%2];"
        : "=r"(r[0]), "=r"(r[1]) : "r"(addr));
}
__device__ __forceinline__ void mma16816(float* d, const u32* a, const u32* b) {
    asm volatile("mma.sync.aligned.m16n8k16.row.col.f32.f16.f16.f32 "
        "{%0,%1,%2,%3}, {%4,%5,%6,%7}, {%8,%9}, {%0,%1,%2,%3};"
        : "+f"(d[0]), "+f"(d[1]), "+f"(d[2]), "+f"(d[3])
        : "r"(a[0]), "r"(a[1]), "r"(a[2]), "r"(a[3]), "r"(b[0]), "r"(b[1]));
}

__device__ __forceinline__ float ex2a(float x) { float r; asm("ex2.approx.f32 %0, %1;" : "=f"(r) : "f"(x)); return r; }
__device__ __forceinline__ float rcpa(float x) { float r; asm("rcp.approx.f32 %0, %1;" : "=f"(r) : "f"(x)); return r; }
__device__ __forceinline__ float sigm(float v) { return rcpa(1.0f + ex2a(v * -1.4426950408889634f)); }
__device__ __forceinline__ float tanh_fast(float v) { return fmaf(2.0f, rcpa(1.0f + ex2a(v * -2.8853900817779268f)), -1.0f); }

// ---------------- GRU kernel ----------------

__global__ void __launch_bounds__(CTA_THREADS, 1)
gru_mma_kernel(const float* __restrict__ x_raw,
               const float* __restrict__ w_ih,
               const float* __restrict__ w_hh,
               const float* __restrict__ b_ih,
               const float* __restrict__ b_hh)
{
    extern __shared__ char sm[];
    const u32 smb = smem_u32(sm);
    const int tid = threadIdx.x;
    const int lane = tid & 31;
    const int wid = tid >> 5;
    const int q = wid & 3;                  // m-tile selector (gate-row block)
    const int grp = wid >> 2;               // group 0..2 -> node tiles {2g, 2g+1}
    const int nt0 = grp * 2;
    const int bar_id = 1 + grp;
    const int gn0 = blockIdx.x * NODES_CTA;

    // ---- stage W_hh fp16 splits (192 x 64, 144B row stride) ----
    for (int i = tid; i < 192 * 64; i += CTA_THREADS) {
        int r = i >> 6, k = i & 63;
        float w = w_hh[i];
        __half hi = __float2half_rn(w);
        __half lo = __float2half_rn(w - __half2float(hi));
        u32 off = (u32)(r * ROW_STRIDE + k * 2);
        *(__half*)(sm + SM_W_HI + off) = hi;
        *(__half*)(sm + SM_W_LO + off) = lo;
    }
    // ---- zero h tiles (both buffers) ----
    for (int i = tid; i < 13824 / 4; i += CTA_THREADS)
        ((u32*)(sm + SM_H))[i] = 0u;
    // ---- stage x transposed: xs[t*48 + n] ----
    {
        float* xs = (float*)(sm + SM_X);
        for (int i = tid; i < NODES_CTA * T_LEN; i += CTA_THREADS) {
            int n = i / T_LEN, tt = i - n * T_LEN;
            xs[tt * NODES_CTA + n] = x_raw[(size_t)(gn0 + n) * T_LEN + tt];
        }
    }
    __syncthreads();

    // ---- W fragments: wa_hi resident; wa_lo via 3 bases + 4 shared offsets ----
    u32 wa_hi[3][4][4];
    u32 wlobase[3];
    u32 wko[4];
    {
        int g = lane >> 3;
        int sub_m = (g & 1) * 8;
        int sub_kb = (g >> 1) * 16;
#pragma unroll
        for (int kc = 0; kc < 4; kc++)
            wko[kc] = (u32)(kc * 32 + sub_kb);
#pragma unroll
        for (int mt = 0; mt < 3; mt++) {
            int row = 64 * mt + 16 * q + sub_m + (lane & 7);
            wlobase[mt] = smb + SM_W_LO + (u32)row * ROW_STRIDE;
            u32 hibase = smb + SM_W_HI + (u32)row * ROW_STRIDE;
#pragma unroll
            for (int kc = 0; kc < 4; kc++)
                ldsm_x4(wa_hi[mt][kc], hibase + wko[kc]);
        }
    }

    // ---- per-thread gate constants: units u_a = 16q + lane/4, u_b = u_a+8 ----
    const int u_a = 16 * q + (lane >> 2);
    const int u_b = u_a + 8;
    const float cwr_a = w_ih[u_a],        cwr_b = w_ih[u_b];
    const float cwz_a = w_ih[64 + u_a],   cwz_b = w_ih[64 + u_b];
    const float cwn_a = w_ih[128 + u_a],  cwn_b = w_ih[128 + u_b];
    const float cr_a  = b_ih[u_a] + b_hh[u_a];
    const float cr_b  = b_ih[u_b] + b_hh[u_b];
    const float cz_a  = b_ih[64 + u_a] + b_hh[64 + u_a];
    const float cz_b  = b_ih[64 + u_b] + b_hh[64 + u_b];
    const float cbin_a = b_ih[128 + u_a], cbin_b = b_ih[128 + u_b];
    const float cbhn_a = b_hh[128 + u_a], cbhn_b = b_hh[128 + u_b];

    // ---- h-fragment (B operand) lane addressing ----
    const int l15 = lane & 15;
    const int r7 = l15 & 7;
    u32 ko[4];
#pragma unroll
    for (int kc = 0; kc < 4; kc++)
        ko[kc] = (u32)(kc * 32 + ((l15 >> 3) * 16));
    const u32 hrow_off = (u32)r7 * ROW_STRIDE;

    const int nc = 2 * (lane & 3);
    const float* xs = (const float*)(sm + SM_X);

    float hprev[2][4];
#pragma unroll
    for (int j = 0; j < 2; j++)
#pragma unroll
        for (int i = 0; i < 4; i++) hprev[j][i] = 0.0f;

#pragma unroll 1
    for (int t = 0; t < T_LEN; t++) {
        const int buf = t & 1;
        const u32 rd = smb + SM_H + (u32)buf * H_BUF_BYTES;
        char* wr = sm + SM_H + (buf ^ 1) * H_BUF_BYTES;
        const float* xrow = xs + t * NODES_CTA;

#pragma unroll
        for (int j = 0; j < 2; j++) {
            const int nt = nt0 + j;
            // ---- load h fragments for this tile ----
            u32 hh[4][2];
            u32 base = (u32)(nt * 8) * ROW_STRIDE + hrow_off;
#pragma unroll
            for (int kc = 0; kc < 4; kc++)
                ldsm_x2(hh[kc], rd + base + ko[kc]);
            // ---- 2-term mma: 3 accumulator chains interleaved ----
            float acc[3][4];
#pragma unroll
            for (int mt = 0; mt < 3; mt++)
#pragma unroll
                for (int i = 0; i < 4; i++) acc[mt][i] = 0.0f;
#pragma unroll
            for (int kc = 0; kc < 4; kc++) {
                u32 wlo3[3][4];
#pragma unroll
                for (int mt = 0; mt < 3; mt++) ldsm_x4(wlo3[mt], wlobase[mt] + wko[kc]);
#pragma unroll
                for (int mt = 0; mt < 3; mt++) mma16816(acc[mt], wa_hi[mt][kc], hh[kc]);
#pragma unroll
                for (int mt = 0; mt < 3; mt++) mma16816(acc[mt], wlo3[mt], hh[kc]);
            }
            // ---- gates (registers only) ----
            const int n_a = nt * 8 + nc;
            const float xva = xrow[n_a];
            const float xvb = xrow[n_a + 1];
#pragma unroll
            for (int i = 0; i < 4; i++) {
                const bool ub = (i >= 2);
                const float x = (i & 1) ? xvb : xva;
                const float cwr = ub ? cwr_b : cwr_a;
                const float cwz = ub ? cwz_b : cwz_a;
                const float cwn = ub ? cwn_b : cwn_a;
                const float cr  = ub ? cr_b  : cr_a;
                const float cz  = ub ? cz_b  : cz_a;
                const float cbin = ub ? cbin_b : cbin_a;
                const float cbhn = ub ? cbhn_b : cbhn_a;

                float rr = sigm(acc[0][i] + fmaf(x, cwr, cr));
                float zz = sigm(acc[1][i] + fmaf(x, cwz, cz));
                float nn = tanh_fast(fmaf(rr, acc[2][i] + cbhn, fmaf(x, cwn, cbin)));
                float hp = hprev[j][i];
                float hn = fmaf(zz, hp - nn, nn);
                hprev[j][i] = hn;

                int node = n_a + (i & 1);
                int u = ub ? u_b : u_a;
                u32 off = (u32)(node * ROW_STRIDE + u * 2);
                *(__half*)(wr + off) = __float2half_rn(hn);
            }
        }
        // per-group barrier (groups are independent: disjoint h tiles)
        asm volatile("bar.sync %0, %1;" :: "r"(bar_id), "r"(128) : "memory");
    }

    // ---- write final h ----
#pragma unroll
    for (int j = 0; j < 2; j++) {
#pragma unroll
        for (int i = 0; i < 4; i++) {
            int node = (nt0 + j) * 8 + nc + (i & 1);
            int u = (i >= 2) ? u_b : u_a;
            g_h[(size_t)(gn0 + node) * 64 + u] = hprev[j][i];
        }
    }
}

// ---------------- collapsed GCN head ----------------

__global__ void __launch_bounds__(128)
head_kernel(const float* __restrict__ W1, const float* __restrict__ b1,
            const float* __restrict__ W2, const float* __restrict__ b2,
            const float* __restrict__ Wfc, const float* __restrict__ bfc,
            float* __restrict__ out)
{
    __shared__ float hbar[64];
    __shared__ float x1s[128];
    __shared__ float x2s[128];
    int g = blockIdx.x, tid = threadIdx.x;

    if (tid < 64) {
        float s = 0.0f;
#pragma unroll
        for (int l = 0; l < 12; l++)
            s += g_h[(size_t)(g * 12 + l) * 64 + tid];
        hbar[tid] = s * (1.0f / 12.0f);
    }
    __syncthreads();

    float s = b1[tid];
#pragma unroll
    for (int k = 0; k < 64; k++)
        s = fmaf(hbar[k], W1[k * 128 + tid], s);
    x1s[tid] = fmaxf(s, 0.0f);
    __syncthreads();

    float s2 = b2[tid];
#pragma unroll
    for (int k = 0; k < 128; k++)
        s2 = fmaf(x1s[k], W2[k * 128 + tid], s2);
    x2s[tid] = fmaxf(s2, 0.0f);
    __syncthreads();

    if (tid < 5) {
        float o = bfc[tid];
#pragma unroll
        for (int k = 0; k < 128; k++)
            o = fmaf(x2s[k], Wfc[k * 5 + tid], o);
        out[g * 5 + tid] = o;
    }
}

// ---------------- launch ----------------
// metadata order: 0 x_raw, 1 edge_index, 2 batch, 3 w_ih, 4 w_hh, 5 b_ih,
//                 6 b_hh, 7 W1, 8 b1, 9 W2, 10 b2, 11 Wfc, 12 bfc

extern "C" void kernel_launch(void* const* d_in, const int* in_sizes, int n_in,
                              void* d_out, int out_size)
{
    const float* x_raw = (const float*)d_in[0];
    const float* w_ih  = (const float*)d_in[3];
    const float* w_hh  = (const float*)d_in[4];
    const float* b_ih  = (const float*)d_in[5];
    const float* b_hh  = (const float*)d_in[6];
    const float* W1    = (const float*)d_in[7];
    const float* b1    = (const float*)d_in[8];
    const float* W2    = (const float*)d_in[9];
    const float* b2    = (const float*)d_in[10];
    const float* Wfc   = (const float*)d_in[11];
    const float* bfc   = (const float*)d_in[12];
    float* out = (float*)d_out;

    cudaFuncSetAttribute(gru_mma_kernel, cudaFuncAttributeMaxDynamicSharedMemorySize, SMEM_TOTAL);

    gru_mma_kernel<<<NCTA, CTA_THREADS, SMEM_TOTAL>>>(x_raw, w_ih, w_hh, b_ih, b_hh);
    head_kernel<<<512, 128>>>(W1, b1, W2, b2, Wfc, bfc, out);
}

// round 11
// speedup vs baseline: 2.9380x; 2.4141x over previous
#include <cuda_runtime.h>
#include <cuda_fp16.h>
#include <cstdint>

// ============================================================================
// ECGRGNN via warp-level mma.sync (base sm_100; tcgen05 unavailable here).
//
// R11: spend the 55x error margin (R10 rel_err 1.8e-5) on the two binding
// floors:
//  (1) 1-term W: pure fp16 weights (drop Wlo*h). Tensor work halves
//      (24 mma/warp/step); W-quant error is systematic 2^-12 -> predicted
//      final rel_err ~1e-4, under the 1e-3 gate.
//  (2) tanh.approx.f32 (MUFU-native, sm_75+): sigmoid = 0.5*tanh(v/2)+0.5,
//      tanh direct. 6 -> 3 MUFU per gate element (MUFU floor 1152->576).
// Structure = R8/R9: 12 warps (3/SMSP), 3 groups x 4 warps x 2 node tiles,
// 144B padded-stride tiles (conflict-free), per-group named barriers,
// gates entirely in registers, fp32 recurrence state in registers.
// ============================================================================

#define T_LEN 500
#define N_NODES 6144
#define NCTA 128
#define NODES_CTA 48
#define CTA_THREADS 384

#define ROW_STRIDE 144               // 128B data + 16B pad: 4-bank rotation/row

typedef uint32_t u32;

__device__ float g_h[N_NODES * 64];

// ---------------- SMEM layout (byte offsets) ----------------
#define SM_W    0                    // 192 rows x 144B               27648
#define SM_H    27648                // 2 buf x 48x144B               13824
#define H_BUF_BYTES 6912             // one buffer (fp16 h)
#define SM_X    41472                // 500 x 48 f32                  96000
#define SMEM_TOTAL 137472

// ---------------- helpers ----------------

__device__ __forceinline__ u32 smem_u32(const void* p) {
    u32 a;
    asm("{ .reg .u64 t; cvta.to.shared.u64 t, %1; cvt.u32.u64 %0, t; }" : "=r"(a) : "l"(p));
    return a;
}

__device__ __forceinline__ void ldsm_x4(u32* r, u32 addr) {
    asm volatile("ldmatrix.sync.aligned.m8n8.x4.shared.b16 {%0,%1,%2,%3}, [%4];"
        : "=r"(r[0]), "=r"(r[1]), "=r"(r[2]), "=r"(r[3]) : "r"(addr));
}
__device__ __forceinline__ void ldsm_x2(u32* r, u32 addr) {
    asm volatile("ldmatrix.sync.aligned.m8n8.x2.shared.b16 {%0,%1}, [%2];"
        : "=r"(r[0]), "=r"(r[1]) : "r"(addr));
}
__device__ __forceinline__ void mma16816(float* d, const u32* a, const u32* b) {
    asm volatile("mma.sync.aligned.m16n8k16.row.col.f32.f16.f16.f32 "
        "{%0,%1,%2,%3}, {%4,%5,%6,%7}, {%8,%9}, {%0,%1,%2,%3};"
        : "+f"(d[0]), "+f"(d[1]), "+f"(d[2]), "+f"(d[3])
        : "r"(a[0]), "r"(a[1]), "r"(a[2]), "r"(a[3]), "r"(b[0]), "r"(b[1]));
}

// MUFU-native tanh (1 op); sigmoid via tanh identity (1 MUFU + FMA)
__device__ __forceinline__ float tanha(float x) {
    float r;
    asm("tanh.approx.f32 %0, %1;" : "=f"(r) : "f"(x));
    return r;
}
__device__ __forceinline__ float sigm(float v) {
    return fmaf(0.5f, tanha(0.5f * v), 0.5f);
}

// ---------------- GRU kernel ----------------

__global__ void __launch_bounds__(CTA_THREADS, 1)
gru_mma_kernel(const float* __restrict__ x_raw,
               const float* __restrict__ w_ih,
               const float* __restrict__ w_hh,
               const float* __restrict__ b_ih,
               const float* __restrict__ b_hh)
{
    extern __shared__ char sm[];
    const u32 smb = smem_u32(sm);
    const int tid = threadIdx.x;
    const int lane = tid & 31;
    const int wid = tid >> 5;
    const int q = wid & 3;                  // m-tile selector (gate-row block)
    const int grp = wid >> 2;               // group 0..2 -> node tiles {2g, 2g+1}
    const int nt0 = grp * 2;
    const int bar_id = 1 + grp;
    const int gn0 = blockIdx.x * NODES_CTA;

    // ---- stage W_hh fp16 (192 x 64, 144B row stride) ----
    for (int i = tid; i < 192 * 64; i += CTA_THREADS) {
        int r = i >> 6, k = i & 63;
        *(__half*)(sm + SM_W + (u32)(r * ROW_STRIDE + k * 2)) = __float2half_rn(w_hh[i]);
    }
    // ---- zero h tiles (both buffers) ----
    for (int i = tid; i < 13824 / 4; i += CTA_THREADS)
        ((u32*)(sm + SM_H))[i] = 0u;
    // ---- stage x transposed: xs[t*48 + n] ----
    {
        float* xs = (float*)(sm + SM_X);
        for (int i = tid; i < NODES_CTA * T_LEN; i += CTA_THREADS) {
            int n = i / T_LEN, tt = i - n * T_LEN;
            xs[tt * NODES_CTA + n] = x_raw[(size_t)(gn0 + n) * T_LEN + tt];
        }
    }
    __syncthreads();

    // ---- preload W fragments (A operand, row-major m16n8k16) ----
    u32 wa[3][4][4];
    {
        int g = lane >> 3;
        int sub_m = (g & 1) * 8;
        int sub_kb = (g >> 1) * 16;
#pragma unroll
        for (int mt = 0; mt < 3; mt++) {
            int row = 64 * mt + 16 * q + sub_m + (lane & 7);
            u32 base = smb + SM_W + (u32)row * ROW_STRIDE;
#pragma unroll
            for (int kc = 0; kc < 4; kc++)
                ldsm_x4(wa[mt][kc], base + (u32)(kc * 32 + sub_kb));
        }
    }

    // ---- per-thread gate constants: units u_a = 16q + lane/4, u_b = u_a+8 ----
    const int u_a = 16 * q + (lane >> 2);
    const int u_b = u_a + 8;
    const float cwr_a = w_ih[u_a],        cwr_b = w_ih[u_b];
    const float cwz_a = w_ih[64 + u_a],   cwz_b = w_ih[64 + u_b];
    const float cwn_a = w_ih[128 + u_a],  cwn_b = w_ih[128 + u_b];
    const float cr_a  = b_ih[u_a] + b_hh[u_a];
    const float cr_b  = b_ih[u_b] + b_hh[u_b];
    const float cz_a  = b_ih[64 + u_a] + b_hh[64 + u_a];
    const float cz_b  = b_ih[64 + u_b] + b_hh[64 + u_b];
    const float cbin_a = b_ih[128 + u_a], cbin_b = b_ih[128 + u_b];
    const float cbhn_a = b_hh[128 + u_a], cbhn_b = b_hh[128 + u_b];

    // ---- h-fragment (B operand) lane addressing ----
    const int l15 = lane & 15;
    const int r7 = l15 & 7;
    u32 ko[4];
#pragma unroll
    for (int kc = 0; kc < 4; kc++)
        ko[kc] = (u32)(kc * 32 + ((l15 >> 3) * 16));
    const u32 hrow_off = (u32)r7 * ROW_STRIDE;

    const int nc = 2 * (lane & 3);
    const float* xs = (const float*)(sm + SM_X);

    float hprev[2][4];
#pragma unroll
    for (int j = 0; j < 2; j++)
#pragma unroll
        for (int i = 0; i < 4; i++) hprev[j][i] = 0.0f;

#pragma unroll 1
    for (int t = 0; t < T_LEN; t++) {
        const int buf = t & 1;
        const u32 rd = smb + SM_H + (u32)buf * H_BUF_BYTES;
        char* wr = sm + SM_H + (buf ^ 1) * H_BUF_BYTES;
        const float* xrow = xs + t * NODES_CTA;

#pragma unroll
        for (int j = 0; j < 2; j++) {
            const int nt = nt0 + j;
            // ---- load h fragments for this tile ----
            u32 hh[4][2];
            u32 base = (u32)(nt * 8) * ROW_STRIDE + hrow_off;
#pragma unroll
            for (int kc = 0; kc < 4; kc++)
                ldsm_x2(hh[kc], rd + base + ko[kc]);
            // ---- 1-term mma: 3 accumulator chains interleaved ----
            float acc[3][4];
#pragma unroll
            for (int mt = 0; mt < 3; mt++)
#pragma unroll
                for (int i = 0; i < 4; i++) acc[mt][i] = 0.0f;
#pragma unroll
            for (int kc = 0; kc < 4; kc++) {
#pragma unroll
                for (int mt = 0; mt < 3; mt++)
                    mma16816(acc[mt], wa[mt][kc], hh[kc]);
            }
            // ---- gates (registers only; tanh.approx MUFU path) ----
            const int n_a = nt * 8 + nc;
            const float xva = xrow[n_a];
            const float xvb = xrow[n_a + 1];
#pragma unroll
            for (int i = 0; i < 4; i++) {
                const bool ub = (i >= 2);
                const float x = (i & 1) ? xvb : xva;
                const float cwr = ub ? cwr_b : cwr_a;
                const float cwz = ub ? cwz_b : cwz_a;
                const float cwn = ub ? cwn_b : cwn_a;
                const float cr  = ub ? cr_b  : cr_a;
                const float cz  = ub ? cz_b  : cz_a;
                const float cbin = ub ? cbin_b : cbin_a;
                const float cbhn = ub ? cbhn_b : cbhn_a;

                float rr = sigm(acc[0][i] + fmaf(x, cwr, cr));
                float zz = sigm(acc[1][i] + fmaf(x, cwz, cz));
                float nn = tanha(fmaf(rr, acc[2][i] + cbhn, fmaf(x, cwn, cbin)));
                float hp = hprev[j][i];
                float hn = fmaf(zz, hp - nn, nn);
                hprev[j][i] = hn;

                int node = n_a + (i & 1);
                int u = ub ? u_b : u_a;
                u32 off = (u32)(node * ROW_STRIDE + u * 2);
                *(__half*)(wr + off) = __float2half_rn(hn);
            }
        }
        // per-group barrier (groups are independent: disjoint h tiles)
        asm volatile("bar.sync %0, %1;" :: "r"(bar_id), "r"(128) : "memory");
    }

    // ---- write final h ----
#pragma unroll
    for (int j = 0; j < 2; j++) {
#pragma unroll
        for (int i = 0; i < 4; i++) {
            int node = (nt0 + j) * 8 + nc + (i & 1);
            int u = (i >= 2) ? u_b : u_a;
            g_h[(size_t)(gn0 + node) * 64 + u] = hprev[j][i];
        }
    }
}

// ---------------- collapsed GCN head ----------------

__global__ void __launch_bounds__(128)
head_kernel(const float* __restrict__ W1, const float* __restrict__ b1,
            const float* __restrict__ W2, const float* __restrict__ b2,
            const float* __restrict__ Wfc, const float* __restrict__ bfc,
            float* __restrict__ out)
{
    __shared__ float hbar[64];
    __shared__ float x1s[128];
    __shared__ float x2s[128];
    int g = blockIdx.x, tid = threadIdx.x;

    if (tid < 64) {
        float s = 0.0f;
#pragma unroll
        for (int l = 0; l < 12; l++)
            s += g_h[(size_t)(g * 12 + l) * 64 + tid];
        hbar[tid] = s * (1.0f / 12.0f);
    }
    __syncthreads();

    float s = b1[tid];
#pragma unroll
    for (int k = 0; k < 64; k++)
        s = fmaf(hbar[k], W1[k * 128 + tid], s);
    x1s[tid] = fmaxf(s, 0.0f);
    __syncthreads();

    float s2 = b2[tid];
#pragma unroll
    for (int k = 0; k < 128; k++)
        s2 = fmaf(x1s[k], W2[k * 128 + tid], s2);
    x2s[tid] = fmaxf(s2, 0.0f);
    __syncthreads();

    if (tid < 5) {
        float o = bfc[tid];
#pragma unroll
        for (int k = 0; k < 128; k++)
            o = fmaf(x2s[k], Wfc[k * 5 + tid], o);
        out[g * 5 + tid] = o;
    }
}

// ---------------- launch ----------------
// metadata order: 0 x_raw, 1 edge_index, 2 batch, 3 w_ih, 4 w_hh, 5 b_ih,
//                 6 b_hh, 7 W1, 8 b1, 9 W2, 10 b2, 11 Wfc, 12 bfc

extern "C" void kernel_launch(void* const* d_in, const int* in_sizes, int n_in,
                              void* d_out, int out_size)
{
    const float* x_raw = (const float*)d_in[0];
    const float* w_ih  = (const float*)d_in[3];
    const float* w_hh  = (const float*)d_in[4];
    const float* b_ih  = (const float*)d_in[5];
    const float* b_hh  = (const float*)d_in[6];
    const float* W1    = (const float*)d_in[7];
    const float* b1    = (const float*)d_in[8];
    const float* W2    = (const float*)d_in[9];
    const float* b2    = (const float*)d_in[10];
    const float* Wfc   = (const float*)d_in[11];
    const float* bfc   = (const float*)d_in[12];
    float* out = (float*)d_out;

    cudaFuncSetAttribute(gru_mma_kernel, cudaFuncAttributeMaxDynamicSharedMemorySize, SMEM_TOTAL);

    gru_mma_kernel<<<NCTA, CTA_THREADS, SMEM_TOTAL>>>(x_raw, w_ih, w_hh, b_ih, b_hh);
    head_kernel<<<512, 128>>>(W1, b1, W2, b2, Wfc, bfc, out);
}